// round 2
// baseline (speedup 1.0000x reference)
#include <cuda_runtime.h>
#include <cuda_bf16.h>

// Problem constants
#define BB   8
#define LL   1024
#define KNB  30
#define NUM_RBF 16
#define NPOS 16
#define MAXREL 32
#define EDGE 128
#define EDGE_IN (NPOS + NUM_RBF * 25)   // 416
#define NEDGE (BB * LL * KNB)           // 245760
#define E_ELEMS ((size_t)NEDGE * EDGE)  // 31457280

__constant__ int cPI[25] = {0,1,2,3,4,0,0,0,0,1,1,1,4,4,3,1,2,3,4,2,3,4,2,3,2};
__constant__ int cPJ[25] = {0,1,2,3,4,1,2,3,4,2,3,4,2,3,2,0,0,0,0,1,1,1,4,4,3};

// Scratch (static __device__ — no allocations allowed)
__device__ float4 g_atoms[BB * LL * 5];   // [Ca, N, C, O, Cb] per residue
__device__ float4 g_ca[BB * LL];
__device__ int    g_eidx[NEDGE];

// ---------------------------------------------------------------------------
// Kernel A: build atom table (Cb from cross product)
// ---------------------------------------------------------------------------
__global__ void prep_kernel(const float* __restrict__ X) {
    int t = blockIdx.x * blockDim.x + threadIdx.x;
    if (t >= BB * LL) return;
    const float* x = X + (size_t)t * 12;
    float Nx = x[0], Ny = x[1], Nz = x[2];
    float Ax = x[3], Ay = x[4], Az = x[5];   // Ca
    float Cx = x[6], Cy = x[7], Cz = x[8];
    float Ox = x[9], Oy = x[10], Oz = x[11];
    float bx = Ax - Nx, by = Ay - Ny, bz = Az - Nz;
    float cx = Cx - Ax, cy = Cy - Ay, cz = Cz - Az;
    float ax = by * cz - bz * cy;
    float ay = bz * cx - bx * cz;
    float az = bx * cy - by * cx;
    float Bx = -0.58273431f * ax + 0.56802827f * bx - 0.54067466f * cx + Ax;
    float By = -0.58273431f * ay + 0.56802827f * by - 0.54067466f * cy + Ay;
    float Bz = -0.58273431f * az + 0.56802827f * bz - 0.54067466f * cz + Az;
    g_atoms[t * 5 + 0] = make_float4(Ax, Ay, Az, 0.f);
    g_atoms[t * 5 + 1] = make_float4(Nx, Ny, Nz, 0.f);
    g_atoms[t * 5 + 2] = make_float4(Cx, Cy, Cz, 0.f);
    g_atoms[t * 5 + 3] = make_float4(Ox, Oy, Oz, 0.f);
    g_atoms[t * 5 + 4] = make_float4(Bx, By, Bz, 0.f);
    g_ca[t] = make_float4(Ax, Ay, Az, 0.f);
}

// ---------------------------------------------------------------------------
// Kernel B: top-30 nearest neighbors per row. One warp per row.
// Key = (dist_bits << 32) | j  -> min key == (smallest dist, smallest j),
// exactly matching jax.lax.top_k(-D) stable tie-breaking.
// ---------------------------------------------------------------------------
__device__ __forceinline__ unsigned long long kmin64(unsigned long long a,
                                                     unsigned long long b) {
    return a < b ? a : b;
}

__global__ void topk_kernel(float* __restrict__ idx_out_f, int write_idx_f) {
    __shared__ unsigned long long keys[LL];
    int row = blockIdx.x;                 // b*L + i
    int lane = threadIdx.x;
    int b = row >> 10;                    // L = 1024
    int base = b * LL;
    float4 ci = g_ca[row];

    for (int j = lane; j < LL; j += 32) {
        float4 cj = g_ca[base + j];
        float dx = ci.x - cj.x, dy = ci.y - cj.y, dz = ci.z - cj.z;
        float dist = sqrtf(dx * dx + dy * dy + dz * dz + 1e-6f);
        keys[j] = ((unsigned long long)__float_as_uint(dist) << 32) | (unsigned)j;
    }
    __syncwarp();

    for (int kk = 0; kk < KNB; kk++) {
        unsigned long long best = ~0ull;
        for (int j = lane; j < LL; j += 32) best = kmin64(best, keys[j]);
        #pragma unroll
        for (int off = 16; off; off >>= 1)
            best = kmin64(best, __shfl_xor_sync(0xffffffffu, best, off));
        unsigned j = (unsigned)(best & 0xffffffffu);
        if (lane == 0) {
            g_eidx[row * KNB + kk] = (int)j;
            if (write_idx_f) idx_out_f[row * KNB + kk] = (float)j;
            keys[j] = ~0ull;
        }
        __syncwarp();
    }
}

// ---------------------------------------------------------------------------
// Kernel C: edge features -> 416x128 matvec (f32x2 packed FMA) -> LayerNorm.
// One warp handles 4 edges (amortizes W_edge L1 traffic 4x).
// Block = 128 threads = 4 warps = 16 edges.
// ---------------------------------------------------------------------------
__device__ __forceinline__ unsigned long long pack2(float a, float b) {
    unsigned long long r;
    asm("mov.b64 %0, {%1, %2};" : "=l"(r) : "f"(a), "f"(b));
    return r;
}
__device__ __forceinline__ void fma2(unsigned long long& d,
                                     unsigned long long a,
                                     unsigned long long b) {
    asm("fma.rn.f32x2 %0, %1, %2, %0;" : "+l"(d) : "l"(a), "l"(b));
}
__device__ __forceinline__ float2 unpack2(unsigned long long v) {
    float lo, hi;
    asm("mov.b64 {%0, %1}, %2;" : "=f"(lo), "=f"(hi) : "l"(v));
    return make_float2(lo, hi);
}

__global__ __launch_bounds__(128) void edge_kernel(
    const int* __restrict__ res_idx,
    const float* __restrict__ W_pos,
    const float* __restrict__ b_pos,
    const float* __restrict__ W_edge,
    const float* __restrict__ ln_gamma,
    const float* __restrict__ ln_beta,
    float* __restrict__ outE) {

    __shared__ float4 fsh[4][EDGE_IN];   // [warp][t] -> 4 edges' feature t
    __shared__ float  dsh[4][4][25];     // [warp][edge][pair]

    int w = threadIdx.x >> 5;
    int lane = threadIdx.x & 31;
    int eBase = (blockIdx.x * 4 + w) * 4;

    // ---- feature construction for 4 edges ----
    #pragma unroll
    for (int q = 0; q < 4; q++) {
        int e = eBase + q;
        int row = e / KNB;               // b*L + i
        int b = row >> 10;
        int j = g_eidx[e];
        if (lane < 25) {
            float4 pi = g_atoms[row * 5 + cPI[lane]];
            float4 pj = g_atoms[(b * LL + j) * 5 + cPJ[lane]];
            float dx = pi.x - pj.x, dy = pi.y - pj.y, dz = pi.z - pj.z;
            dsh[w][q][lane] = sqrtf(dx * dx + dy * dy + dz * dz + 1e-6f);
        }
        if (lane < NPOS) {
            int off = res_idx[row] - res_idx[b * LL + j];
            int dpos = off + MAXREL;
            dpos = dpos < 0 ? 0 : (dpos > 2 * MAXREL ? 2 * MAXREL : dpos);
            ((float*)&fsh[w][lane])[q] = W_pos[dpos * NPOS + lane] + b_pos[lane];
        }
    }
    __syncwarp();

    #pragma unroll
    for (int q = 0; q < 4; q++) {
        for (int t = lane; t < 25 * NUM_RBF; t += 32) {
            int p = t >> 4, m = t & 15;
            float mu = 2.0f + (float)m * (20.0f / 15.0f);
            float xr = (dsh[w][q][p] - mu) * (1.0f / 1.25f);
            ((float*)&fsh[w][NPOS + t])[q] = expf(-xr * xr);
        }
    }
    __syncwarp();

    // ---- matvec: E[c] = sum_t f[t] * W_edge[t*128 + c] ----
    // lane owns channels c = lane*4 .. lane*4+3
    unsigned long long acc00 = 0, acc01 = 0, acc10 = 0, acc11 = 0;
    unsigned long long acc20 = 0, acc21 = 0, acc30 = 0, acc31 = 0;
    const ulonglong2* wp = reinterpret_cast<const ulonglong2*>(W_edge) + lane;
    const float4* frow = fsh[w];

    #pragma unroll 4
    for (int t = 0; t < EDGE_IN; t++) {
        float4 fv = frow[t];
        ulonglong2 wv = wp[t * 32];      // (w0,w1),(w2,w3) for this lane
        unsigned long long f0 = pack2(fv.x, fv.x);
        unsigned long long f1 = pack2(fv.y, fv.y);
        unsigned long long f2 = pack2(fv.z, fv.z);
        unsigned long long f3 = pack2(fv.w, fv.w);
        fma2(acc00, f0, wv.x); fma2(acc01, f0, wv.y);
        fma2(acc10, f1, wv.x); fma2(acc11, f1, wv.y);
        fma2(acc20, f2, wv.x); fma2(acc21, f2, wv.y);
        fma2(acc30, f3, wv.x); fma2(acc31, f3, wv.y);
    }

    // ---- LayerNorm + store per edge ----
    float4 g4 = reinterpret_cast<const float4*>(ln_gamma)[lane];
    float4 b4 = reinterpret_cast<const float4*>(ln_beta)[lane];
    float4* out4 = reinterpret_cast<float4*>(outE);

    unsigned long long accs[4][2] = {{acc00, acc01}, {acc10, acc11},
                                     {acc20, acc21}, {acc30, acc31}};
    #pragma unroll
    for (int q = 0; q < 4; q++) {
        float2 p0 = unpack2(accs[q][0]);
        float2 p1 = unpack2(accs[q][1]);
        float v0 = p0.x, v1 = p0.y, v2 = p1.x, v3 = p1.y;
        float s = v0 + v1 + v2 + v3;
        #pragma unroll
        for (int off = 16; off; off >>= 1)
            s += __shfl_xor_sync(0xffffffffu, s, off);
        float mean = s * (1.0f / 128.0f);
        float d0 = v0 - mean, d1 = v1 - mean, d2 = v2 - mean, d3 = v3 - mean;
        float sq = d0 * d0 + d1 * d1 + d2 * d2 + d3 * d3;
        #pragma unroll
        for (int off = 16; off; off >>= 1)
            sq += __shfl_xor_sync(0xffffffffu, sq, off);
        float inv = rsqrtf(sq * (1.0f / 128.0f) + 1e-5f);
        float4 o;
        o.x = d0 * inv * g4.x + b4.x;
        o.y = d1 * inv * g4.y + b4.y;
        o.z = d2 * inv * g4.z + b4.z;
        o.w = d3 * inv * g4.w + b4.w;
        out4[(size_t)(eBase + q) * 32 + lane] = o;
    }
}

// ---------------------------------------------------------------------------
// Launch. Input order (setup_inputs dict order):
// 0:X 1:mask 2:residue_idx 3:S 4:SSE3 5:SSE8 6:W_pos 7:b_pos 8:W_edge
// 9:ln_gamma 10:ln_beta.  Output: E (f32, B*L*K*128) then E_idx as f32 (B*L*K).
// ---------------------------------------------------------------------------
extern "C" void kernel_launch(void* const* d_in, const int* in_sizes, int n_in,
                              void* d_out, int out_size) {
    const float* X        = (const float*)d_in[0];
    const int*   res_idx  = (const int*)  d_in[2];
    const float* W_pos    = (const float*)d_in[6];
    const float* b_pos    = (const float*)d_in[7];
    const float* W_edge   = (const float*)d_in[8];
    const float* ln_gamma = (const float*)d_in[9];
    const float* ln_beta  = (const float*)d_in[10];

    float* outE = (float*)d_out;
    int write_idx = (size_t)out_size >= E_ELEMS + (size_t)NEDGE;
    float* idx_out_f = write_idx ? outE + E_ELEMS : nullptr;

    prep_kernel<<<(BB * LL + 255) / 256, 256>>>(X);
    topk_kernel<<<BB * LL, 32>>>(idx_out_f, write_idx);
    edge_kernel<<<NEDGE / 16, 128>>>(res_idx, W_pos, b_pos, W_edge,
                                     ln_gamma, ln_beta, outE);
}